// round 4
// baseline (speedup 1.0000x reference)
#include <cuda_runtime.h>
#include <cuda_fp16.h>
#include <math.h>

// ---------------------------------------------------------------------------
// 2-layer LSTM, H=1024, T=4096 sequential steps.
//   g0_kernel : precompute G0[t] = W_ih0 @ xin[t] + b_ih0 + b_hh0 (parallel).
//   lstm_kernel: ONE persistent kernel, 143 co-resident CTAs.
//     CTAs 0..48  : layer-0 units, W_hh0 fp16 in SMEM.
//     CTAs 49..142: layer-1 units, [W_ih1|W_hh1] fp16 in SMEM.
// ROUND-4 REWRITE (correctness hardening):
//   * h history is monotonic: g_H0[t+1], g_H1[t+1] written once per step.
//     => zero WAR hazards, no ping-pong parity, no stale-line reuse possible.
//   * publish/consume uses PTX acquire/release (red.release.gpu /
//     ld.acquire.gpu) instead of raw .cv polling + threadfence.
//   * input pointers bound by element count (immune to harness reordering
//     of size-distinguishable inputs).
// ---------------------------------------------------------------------------

#define H        1024
#define T_STEPS  4096
#define GATES    4096
#define NA       49          // layer-0 CTAs
#define NUA      21          // units per layer-0 CTA (last ragged: 16)
#define NB       94          // layer-1 CTAs
#define NUB      11          // units per layer-1 CTA (last ragged: 1)
#define GRID     (NA + NB)   // 143
#define THREADS  512
#define BASE_OUT ((size_t)T_STEPS * H)

// ---- shared memory layout (byte offsets; sized to the max CTA) ----
#define A_W_BYTES (NUA * 4 * H * 2)            // 172032 fp16 weight rows
#define A_HB_OFF  (A_W_BYTES)
#define A_SG_OFF  (A_HB_OFF + H * 4)
#define A_SC_OFF  (A_SG_OFF + NUA * 4 * 4)
#define A_TOTAL   (A_SC_OFF + NUA * 4)

#define B_W_BYTES (NUB * 4 * 2 * H * 2)        // 180224
#define B_HB_OFF  (B_W_BYTES)
#define B_SG_OFF  (B_HB_OFF + 2 * H * 4)
#define B_SC_OFF  (B_SG_OFF + NUB * 4 * 4)
#define B_SB_OFF  (B_SC_OFF + NUB * 4)
#define B_TOTAL   (B_SB_OFF + NUB * 4 * 4)

#define SMEM_BYTES (B_TOTAL > A_TOTAL ? B_TOTAL : A_TOTAL)   // ~184.4 KB

// ---- device-global scratch ----
__device__ float    g_G0[(size_t)T_STEPS * GATES];     // 64 MB
__device__ float    g_H0[(size_t)(T_STEPS + 1) * H];   // layer-0 h history
__device__ float    g_H1[(size_t)(T_STEPS + 1) * H];   // layer-1 h history
__device__ unsigned g_cntA;
__device__ unsigned g_cntB;

__device__ __forceinline__ unsigned ld_acquire(const unsigned* p) {
    unsigned v;
    asm volatile("ld.acquire.gpu.global.u32 %0, [%1];"
                 : "=r"(v) : "l"(p) : "memory");
    return v;
}
__device__ __forceinline__ void red_release_add1(unsigned* p) {
    asm volatile("red.release.gpu.global.add.u32 [%0], %1;"
                 :: "l"(p), "r"(1u) : "memory");
}

// ---------------------------------------------------------------------------
__global__ void init_kernel(const float* __restrict__ hidden) {
    int u = threadIdx.x;
    if (u < H) {
        g_H0[u] = hidden[u];        // slot 0 = initial h
        g_H1[u] = hidden[H + u];
    }
    if (u == 0) { g_cntA = 0u; g_cntB = 0u; }
}

// ---------------------------------------------------------------------------
// G0[t][j] = sum_k W_ih0[j][k]*xin[t][k] + b_ih0[j] + b_hh0[j]
// xin[t] = [x[t](17) | ip_emb[ip[t][0..7]](8) | port_emb[port[t][0..1]](8)]
__global__ void g0_kernel(const float* __restrict__ x,
                          const int*   __restrict__ ip,
                          const int*   __restrict__ port,
                          const float* __restrict__ ip_emb,
                          const float* __restrict__ port_emb,
                          const float* __restrict__ Wih0,
                          const float* __restrict__ bih0,
                          const float* __restrict__ bhh0) {
    __shared__ float sxin[8][33];
    const int t0  = blockIdx.x * 8;
    const int tid = threadIdx.x;

    for (int idx = tid; idx < 8 * 33; idx += 256) {
        int tt = idx / 33, k = idx - tt * 33;
        int t = t0 + tt;
        float v;
        if (k < 17)      v = x[t * 17 + k];
        else if (k < 25) v = ip_emb[ip[t * 8 + (k - 17)]];
        else {
            int s = (k - 25) >> 2, e = (k - 25) & 3;
            v = port_emb[port[t * 2 + s] * 4 + e];
        }
        sxin[tt][k] = v;
    }
    __syncthreads();

    for (int j = tid; j < GATES; j += 256) {
        float w[33];
#pragma unroll
        for (int k = 0; k < 33; ++k) w[k] = __ldg(&Wih0[j * 33 + k]);
        float bias = __ldg(&bih0[j]) + __ldg(&bhh0[j]);
#pragma unroll
        for (int tt = 0; tt < 8; ++tt) {
            float acc = bias;
#pragma unroll
            for (int k = 0; k < 33; ++k) acc = fmaf(w[k], sxin[tt][k], acc);
            g_G0[(size_t)(t0 + tt) * GATES + j] = acc;
        }
    }
}

// ---------------------------------------------------------------------------
__global__ __launch_bounds__(THREADS, 1)
void lstm_kernel(const float* __restrict__ Whh0,
                 const float* __restrict__ Wih1,
                 const float* __restrict__ Whh1,
                 const float* __restrict__ bih1,
                 const float* __restrict__ bhh1,
                 const float* __restrict__ cell,
                 float* __restrict__ out,
                 int write_state) {
    extern __shared__ char smem[];
    const int tid  = threadIdx.x;
    const int lane = tid & 31;
    const int warp = tid >> 5;
    const int cta  = blockIdx.x;

    if (cta < NA) {
        // =========================== layer 0 ===========================
        const int u0 = cta * NUA;
        const int nu = min(NUA, H - u0);
        __half* sw = (__half*)smem;
        float*  shb = (float*)(smem + A_HB_OFF);
        float*  sg  = (float*)(smem + A_SG_OFF);
        float*  sc  = (float*)(smem + A_SC_OFF);
        const int nrows = 4 * nu;

        for (int idx = tid; idx < nrows * H; idx += THREADS) {
            int r = idx >> 10, k = idx & (H - 1);
            int grow = (r & 3) * H + u0 + (r >> 2);
            sw[idx] = __float2half_rn(Whh0[(size_t)grow * H + k]);
        }
        for (int u = tid; u < nu; u += THREADS) sc[u] = cell[u0 + u];
        __syncthreads();

        for (int t = 0; t < T_STEPS; ++t) {
            if (tid == 0) {
                unsigned need = (unsigned)(NA * t);        // h0(t-1) published
                while (ld_acquire(&g_cntA) < need) {}
            }
            __syncthreads();

            const float* hprev = g_H0 + (size_t)t * H;     // slot t, RAW only
            for (int i = tid; i < H; i += THREADS) shb[i] = __ldcg(&hprev[i]);
            __syncthreads();

            float4 hreg[8];
#pragma unroll
            for (int i = 0; i < 8; ++i)
                hreg[i] = *(const float4*)&shb[i * 128 + lane * 4];

            for (int r = warp; r < nrows; r += 16) {
                const __half* wr = sw + (size_t)r * H;
                float a0 = 0.f, a1 = 0.f, a2 = 0.f, a3 = 0.f;
#pragma unroll
                for (int i = 0; i < 8; ++i) {
                    uint2 wv = *(const uint2*)(wr + i * 128 + lane * 4);
                    float2 f01 = __half22float2(*(__half2*)&wv.x);
                    float2 f23 = __half22float2(*(__half2*)&wv.y);
                    a0 = fmaf(f01.x, hreg[i].x, a0);
                    a1 = fmaf(f01.y, hreg[i].y, a1);
                    a2 = fmaf(f23.x, hreg[i].z, a2);
                    a3 = fmaf(f23.y, hreg[i].w, a3);
                }
                float acc = (a0 + a1) + (a2 + a3);
#pragma unroll
                for (int o = 16; o > 0; o >>= 1)
                    acc += __shfl_xor_sync(0xffffffffu, acc, o);
                if (lane == 0) {
                    int grow = (r & 3) * H + u0 + (r >> 2);
                    sg[r] = acc + __ldg(&g_G0[(size_t)t * GATES + grow]);
                }
            }
            __syncthreads();

            if (tid < nu) {
                float vi = sg[tid * 4 + 0], vf = sg[tid * 4 + 1];
                float vg = sg[tid * 4 + 2], vo = sg[tid * 4 + 3];
                float ii = 1.f / (1.f + expf(-vi));
                float ff = 1.f / (1.f + expf(-vf));
                float gg = tanhf(vg);
                float oo = 1.f / (1.f + expf(-vo));
                float c  = ff * sc[tid] + ii * gg;
                sc[tid]  = c;
                float h  = oo * tanhf(c);
                __stcg(&g_H0[(size_t)(t + 1) * H + u0 + tid], h);
                if (t == T_STEPS - 1 && write_state) {
                    out[BASE_OUT + u0 + tid]         = h;   // hf layer 0
                    out[BASE_OUT + 2 * H + u0 + tid] = c;   // cf layer 0
                }
            }
            __syncthreads();
            if (tid == 0) red_release_add1(&g_cntA);
        }
    } else {
        // =========================== layer 1 ===========================
        const int b  = cta - NA;
        const int u0 = b * NUB;
        const int nu = min(NUB, H - u0);
        __half* sw = (__half*)smem;
        float*  shb = (float*)(smem + B_HB_OFF);
        float*  sg  = (float*)(smem + B_SG_OFF);
        float*  sc  = (float*)(smem + B_SC_OFF);
        float*  sb  = (float*)(smem + B_SB_OFF);
        const int nrows = 4 * nu;

        for (int idx = tid; idx < nrows * 2 * H; idx += THREADS) {
            int r = idx >> 11, k = idx & (2 * H - 1);
            int grow = (r & 3) * H + u0 + (r >> 2);
            float w = (k < H) ? Wih1[(size_t)grow * H + k]
                              : Whh1[(size_t)grow * H + (k - H)];
            sw[idx] = __float2half_rn(w);
        }
        for (int r = tid; r < nrows; r += THREADS) {
            int grow = (r & 3) * H + u0 + (r >> 2);
            sb[r] = bih1[grow] + bhh1[grow];
        }
        for (int u = tid; u < nu; u += THREADS) sc[u] = cell[H + u0 + u];
        __syncthreads();

        for (int t = 0; t < T_STEPS; ++t) {
            if (tid == 0) {
                unsigned needA = (unsigned)(NA * (t + 1));  // h0(t) published
                unsigned needB = (unsigned)(NB * t);        // h1(t-1) published
                while (ld_acquire(&g_cntA) < needA) {}
                while (ld_acquire(&g_cntB) < needB) {}
            }
            __syncthreads();

            const float* h0now  = g_H0 + (size_t)(t + 1) * H;
            const float* h1prev = g_H1 + (size_t)t * H;
            for (int i = tid; i < H; i += THREADS) shb[i]     = __ldcg(&h0now[i]);
            for (int i = tid; i < H; i += THREADS) shb[H + i] = __ldcg(&h1prev[i]);
            __syncthreads();

            float4 hreg[16];
#pragma unroll
            for (int i = 0; i < 16; ++i)
                hreg[i] = *(const float4*)&shb[i * 128 + lane * 4];

            for (int r = warp; r < nrows; r += 16) {
                const __half* wr = sw + (size_t)r * 2 * H;
                float a0 = 0.f, a1 = 0.f, a2 = 0.f, a3 = 0.f;
#pragma unroll
                for (int i = 0; i < 16; ++i) {
                    uint2 wv = *(const uint2*)(wr + i * 128 + lane * 4);
                    float2 f01 = __half22float2(*(__half2*)&wv.x);
                    float2 f23 = __half22float2(*(__half2*)&wv.y);
                    a0 = fmaf(f01.x, hreg[i].x, a0);
                    a1 = fmaf(f01.y, hreg[i].y, a1);
                    a2 = fmaf(f23.x, hreg[i].z, a2);
                    a3 = fmaf(f23.y, hreg[i].w, a3);
                }
                float acc = (a0 + a1) + (a2 + a3);
#pragma unroll
                for (int o = 16; o > 0; o >>= 1)
                    acc += __shfl_xor_sync(0xffffffffu, acc, o);
                if (lane == 0) sg[r] = acc + sb[r];
            }
            __syncthreads();

            if (tid < nu) {
                float vi = sg[tid * 4 + 0], vf = sg[tid * 4 + 1];
                float vg = sg[tid * 4 + 2], vo = sg[tid * 4 + 3];
                float ii = 1.f / (1.f + expf(-vi));
                float ff = 1.f / (1.f + expf(-vf));
                float gg = tanhf(vg);
                float oo = 1.f / (1.f + expf(-vo));
                float c  = ff * sc[tid] + ii * gg;
                sc[tid]  = c;
                float h  = oo * tanhf(c);
                __stcg(&g_H1[(size_t)(t + 1) * H + u0 + tid], h);
                out[(size_t)t * H + u0 + tid] = fmaxf(h, 0.f);
                if (t == T_STEPS - 1 && write_state) {
                    out[BASE_OUT + H + u0 + tid]     = h;   // hf layer 1
                    out[BASE_OUT + 3 * H + u0 + tid] = c;   // cf layer 1
                }
            }
            __syncthreads();
            if (tid == 0) red_release_add1(&g_cntB);
        }
    }
}

// ---------------------------------------------------------------------------
extern "C" void kernel_launch(void* const* d_in, const int* in_sizes, int n_in,
                              void* d_out, int out_size) {
    // -- bind inputs by element count (robust to harness reordering of
    //    size-distinguishable inputs; equal-size groups keep relative order) --
    const float *x = 0, *hidden = 0, *cell = 0, *ip_emb = 0, *port_emb = 0;
    const float *Wih0 = 0, *Whh0 = 0, *bih0 = 0, *bhh0 = 0;
    const float *Wih1 = 0, *Whh1 = 0, *bih1 = 0, *bhh1 = 0;
    const int *ip = 0, *port = 0;

    const float* big[3]  = {0, 0, 0};  int nbig  = 0;  // 4194304: Whh0,Wih1,Whh1
    const float* bias[4] = {0, 0, 0, 0}; int nbias = 0; // 4096: bih0,bhh0,bih1,bhh1
    const float* st2[2]  = {0, 0};     int nst2  = 0;  // 2048: hidden,cell

    for (int i = 0; i < n_in; ++i) {
        switch (in_sizes[i]) {
            case 69632:   x        = (const float*)d_in[i]; break;
            case 32768:   ip       = (const int*)  d_in[i]; break;
            case 8192:    port     = (const int*)  d_in[i]; break;
            case 256:     ip_emb   = (const float*)d_in[i]; break;
            case 280000:  port_emb = (const float*)d_in[i]; break;
            case 135168:  Wih0     = (const float*)d_in[i]; break;
            case 4194304: if (nbig  < 3) big[nbig++]   = (const float*)d_in[i]; break;
            case 4096:    if (nbias < 4) bias[nbias++] = (const float*)d_in[i]; break;
            case 2048:    if (nst2  < 2) st2[nst2++]   = (const float*)d_in[i]; break;
            default: break;
        }
    }
    if (nbig == 3 && nbias == 4 && nst2 == 2 && x && ip && port &&
        ip_emb && port_emb && Wih0) {
        Whh0 = big[0]; Wih1 = big[1]; Whh1 = big[2];
        bih0 = bias[0]; bhh0 = bias[1]; bih1 = bias[2]; bhh1 = bias[3];
        hidden = st2[0]; cell = st2[1];
    } else {
        // positional fallback (reference dict order)
        x        = (const float*)d_in[0];
        ip       = (const int*)  d_in[1];
        port     = (const int*)  d_in[2];
        hidden   = (const float*)d_in[3];
        cell     = (const float*)d_in[4];
        ip_emb   = (const float*)d_in[5];
        port_emb = (const float*)d_in[6];
        Wih0     = (const float*)d_in[7];
        Whh0     = (const float*)d_in[8];
        bih0     = (const float*)d_in[9];
        bhh0     = (const float*)d_in[10];
        Wih1     = (const float*)d_in[11];
        Whh1     = (const float*)d_in[12];
        bih1     = (const float*)d_in[13];
        bhh1     = (const float*)d_in[14];
    }
    float* out = (float*)d_out;
    int write_state = (out_size >= (int)(T_STEPS * H + 4 * H)) ? 1 : 0;

    cudaFuncSetAttribute(lstm_kernel,
                         cudaFuncAttributeMaxDynamicSharedMemorySize,
                         SMEM_BYTES);

    init_kernel<<<1, 1024>>>(hidden);
    g0_kernel<<<T_STEPS / 8, 256>>>(x, ip, port, ip_emb, port_emb,
                                    Wih0, bih0, bhh0);
    lstm_kernel<<<GRID, THREADS, SMEM_BYTES>>>(Whh0, Wih1, Whh1,
                                               bih1, bhh1, cell, out,
                                               write_state);
}

// round 5
// speedup vs baseline: 1.6123x; 1.6123x over previous
#include <cuda_runtime.h>
#include <cuda_fp16.h>
#include <math.h>

// ---------------------------------------------------------------------------
// 2-layer LSTM, H=1024, T=4096 sequential steps.
//   g0_kernel : precompute G0[t] = W_ih0 @ xin[t] + b_ih0 + b_hh0 (parallel).
//   lstm_kernel: ONE persistent kernel, 143 co-resident CTAs.
//     CTAs 0..48  : layer-0 units, W_hh0 fp16 in SMEM.
//     CTAs 49..142: layer-1 units, [W_ih1|W_hh1] fp16 in SMEM.
//   Sync: monotonic h history + acquire/release counters (round-4, proven).
// ROUND-5: HFMA2 inner loop.
//   * h published as fp16 (u16 .cg stores), consumed as packed half2.
//   * dot products via __hfma2, 8 half2 accumulators/lane (chains <= 4 adds),
//     converted to fp32 once per row -> removes the 1-F2F-per-MAC overhead
//     that dominated round 4's issue bandwidth.
//   * conflict-free LDS.128: lane l reads 16B granule (j*32+l) of each row.
// ---------------------------------------------------------------------------

#define H        1024
#define T_STEPS  4096
#define GATES    4096
#define NA       49          // layer-0 CTAs
#define NUA      21          // units per layer-0 CTA (last ragged: 16)
#define NB       94          // layer-1 CTAs
#define NUB      11          // units per layer-1 CTA (last ragged: 1)
#define GRID     (NA + NB)   // 143
#define THREADS  512
#define BASE_OUT ((size_t)T_STEPS * H)

// ---- shared memory layout (byte offsets; sized to the max CTA) ----
#define A_W_BYTES (NUA * 4 * H * 2)            // 172032 fp16 weight rows
#define A_HB_OFF  (A_W_BYTES)                  // 1024 halves staged h0 (2KB)
#define A_SG_OFF  (A_HB_OFF + H * 2)
#define A_SC_OFF  (A_SG_OFF + NUA * 4 * 4)
#define A_TOTAL   (A_SC_OFF + NUA * 4)

#define B_W_BYTES (NUB * 4 * 2 * H * 2)        // 180224
#define B_HB_OFF  (B_W_BYTES)                  // 2048 halves [h0(t) ; h1(t-1)]
#define B_SG_OFF  (B_HB_OFF + 2 * H * 2)
#define B_SC_OFF  (B_SG_OFF + NUB * 4 * 4)
#define B_SB_OFF  (B_SC_OFF + NUB * 4)
#define B_TOTAL   (B_SB_OFF + NUB * 4 * 4)

#define SMEM_BYTES (B_TOTAL > A_TOTAL ? B_TOTAL : A_TOTAL)

// ---- device-global scratch ----
__device__ float          g_G0[(size_t)T_STEPS * GATES];        // 64 MB
__device__ unsigned short g_Hh0[(size_t)(T_STEPS + 1) * H];     // h0 history fp16
__device__ unsigned short g_Hh1[(size_t)(T_STEPS + 1) * H];     // h1 history fp16
__device__ unsigned       g_cntA;
__device__ unsigned       g_cntB;

__device__ __forceinline__ unsigned ld_acquire(const unsigned* p) {
    unsigned v;
    asm volatile("ld.acquire.gpu.global.u32 %0, [%1];"
                 : "=r"(v) : "l"(p) : "memory");
    return v;
}
__device__ __forceinline__ void red_release_add1(unsigned* p) {
    asm volatile("red.release.gpu.global.add.u32 [%0], %1;"
                 :: "l"(p), "r"(1u) : "memory");
}
__device__ __forceinline__ unsigned ldcg_u32(const unsigned* p) {
    unsigned v;
    asm volatile("ld.global.cg.u32 %0, [%1];" : "=r"(v) : "l"(p));
    return v;
}
__device__ __forceinline__ void stcg_u16(unsigned short* p, unsigned short v) {
    asm volatile("st.global.cg.u16 [%0], %1;" :: "l"(p), "h"(v));
}

// 4 HFMA2 on a 16B weight granule against a 16B h granule
__device__ __forceinline__ void mac_granule(const uint4& wq, const uint4& hq,
                                            __half2* acc) {
    acc[0] = __hfma2(*(const __half2*)&wq.x, *(const __half2*)&hq.x, acc[0]);
    acc[1] = __hfma2(*(const __half2*)&wq.y, *(const __half2*)&hq.y, acc[1]);
    acc[2] = __hfma2(*(const __half2*)&wq.z, *(const __half2*)&hq.z, acc[2]);
    acc[3] = __hfma2(*(const __half2*)&wq.w, *(const __half2*)&hq.w, acc[3]);
}

__device__ __forceinline__ float acc8_to_float(const __half2* acc) {
    float s = 0.f;
#pragma unroll
    for (int q = 0; q < 8; ++q) {
        float2 f = __half22float2(acc[q]);
        s += f.x + f.y;
    }
    return s;
}

// ---------------------------------------------------------------------------
__global__ void init_kernel(const float* __restrict__ hidden) {
    int u = threadIdx.x;
    if (u < H) {
        g_Hh0[u] = __half_as_ushort(__float2half_rn(hidden[u]));
        g_Hh1[u] = __half_as_ushort(__float2half_rn(hidden[H + u]));
    }
    if (u == 0) { g_cntA = 0u; g_cntB = 0u; }
}

// ---------------------------------------------------------------------------
// G0[t][j] = sum_k W_ih0[j][k]*xin[t][k] + b_ih0[j] + b_hh0[j]
__global__ void g0_kernel(const float* __restrict__ x,
                          const int*   __restrict__ ip,
                          const int*   __restrict__ port,
                          const float* __restrict__ ip_emb,
                          const float* __restrict__ port_emb,
                          const float* __restrict__ Wih0,
                          const float* __restrict__ bih0,
                          const float* __restrict__ bhh0) {
    __shared__ float sxin[8][33];
    const int t0  = blockIdx.x * 8;
    const int tid = threadIdx.x;

    for (int idx = tid; idx < 8 * 33; idx += 256) {
        int tt = idx / 33, k = idx - tt * 33;
        int t = t0 + tt;
        float v;
        if (k < 17)      v = x[t * 17 + k];
        else if (k < 25) v = ip_emb[ip[t * 8 + (k - 17)]];
        else {
            int s = (k - 25) >> 2, e = (k - 25) & 3;
            v = port_emb[port[t * 2 + s] * 4 + e];
        }
        sxin[tt][k] = v;
    }
    __syncthreads();

    for (int j = tid; j < GATES; j += 256) {
        float w[33];
#pragma unroll
        for (int k = 0; k < 33; ++k) w[k] = __ldg(&Wih0[j * 33 + k]);
        float bias = __ldg(&bih0[j]) + __ldg(&bhh0[j]);
#pragma unroll
        for (int tt = 0; tt < 8; ++tt) {
            float acc = bias;
#pragma unroll
            for (int k = 0; k < 33; ++k) acc = fmaf(w[k], sxin[tt][k], acc);
            g_G0[(size_t)(t0 + tt) * GATES + j] = acc;
        }
    }
}

// ---------------------------------------------------------------------------
__global__ __launch_bounds__(THREADS, 1)
void lstm_kernel(const float* __restrict__ Whh0,
                 const float* __restrict__ Wih1,
                 const float* __restrict__ Whh1,
                 const float* __restrict__ bih1,
                 const float* __restrict__ bhh1,
                 const float* __restrict__ cell,
                 float* __restrict__ out,
                 int write_state) {
    extern __shared__ char smem[];
    const int tid  = threadIdx.x;
    const int lane = tid & 31;
    const int warp = tid >> 5;
    const int cta  = blockIdx.x;

    if (cta < NA) {
        // =========================== layer 0 ===========================
        const int u0 = cta * NUA;
        const int nu = min(NUA, H - u0);
        __half* sw  = (__half*)smem;
        unsigned* shb2 = (unsigned*)(smem + A_HB_OFF);     // 512 uint = 1024 h
        float*  sg  = (float*)(smem + A_SG_OFF);
        float*  sc  = (float*)(smem + A_SC_OFF);
        const int nrows = 4 * nu;

        for (int idx = tid; idx < nrows * H; idx += THREADS) {
            int r = idx >> 10, k = idx & (H - 1);
            int grow = (r & 3) * H + u0 + (r >> 2);
            sw[idx] = __float2half_rn(Whh0[(size_t)grow * H + k]);
        }
        for (int u = tid; u < nu; u += THREADS) sc[u] = cell[u0 + u];
        __syncthreads();

        for (int t = 0; t < T_STEPS; ++t) {
            if (tid == 0) {
                unsigned need = (unsigned)(NA * t);
                while (ld_acquire(&g_cntA) < need) {}
            }
            __syncthreads();

            const unsigned* hsrc = (const unsigned*)(g_Hh0 + (size_t)t * H);
            shb2[tid] = ldcg_u32(&hsrc[tid]);   // THREADS==512 exactly
            __syncthreads();

            uint4 hq[4];
#pragma unroll
            for (int j = 0; j < 4; ++j)
                hq[j] = ((const uint4*)shb2)[j * 32 + lane];

            for (int r = warp; r < nrows; r += 16) {
                const uint4* wq = (const uint4*)(sw + (size_t)r * H);
                __half2 acc[8];
#pragma unroll
                for (int q = 0; q < 8; ++q) acc[q] = __float2half2_rn(0.f);
#pragma unroll
                for (int j = 0; j < 4; ++j)
                    mac_granule(wq[j * 32 + lane], hq[j], acc + (j & 1) * 4);
                float s = acc8_to_float(acc);
#pragma unroll
                for (int o = 16; o > 0; o >>= 1)
                    s += __shfl_xor_sync(0xffffffffu, s, o);
                if (lane == 0) {
                    int grow = (r & 3) * H + u0 + (r >> 2);
                    sg[r] = s + __ldg(&g_G0[(size_t)t * GATES + grow]);
                }
            }
            __syncthreads();

            if (tid < nu) {
                float vi = sg[tid * 4 + 0], vf = sg[tid * 4 + 1];
                float vg = sg[tid * 4 + 2], vo = sg[tid * 4 + 3];
                float ii = 1.f / (1.f + expf(-vi));
                float ff = 1.f / (1.f + expf(-vf));
                float gg = tanhf(vg);
                float oo = 1.f / (1.f + expf(-vo));
                float c  = ff * sc[tid] + ii * gg;
                sc[tid]  = c;
                float h  = oo * tanhf(c);
                stcg_u16(&g_Hh0[(size_t)(t + 1) * H + u0 + tid],
                         __half_as_ushort(__float2half_rn(h)));
                if (t == T_STEPS - 1 && write_state) {
                    out[BASE_OUT + u0 + tid]         = h;   // hf layer 0
                    out[BASE_OUT + 2 * H + u0 + tid] = c;   // cf layer 0
                }
            }
            __syncthreads();
            if (tid == 0) red_release_add1(&g_cntA);
        }
    } else {
        // =========================== layer 1 ===========================
        const int b  = cta - NA;
        const int u0 = b * NUB;
        const int nu = min(NUB, H - u0);
        __half* sw  = (__half*)smem;
        unsigned* shb2 = (unsigned*)(smem + B_HB_OFF);     // 1024 uint = 2048 h
        float*  sg  = (float*)(smem + B_SG_OFF);
        float*  sc  = (float*)(smem + B_SC_OFF);
        float*  sb  = (float*)(smem + B_SB_OFF);
        const int nrows = 4 * nu;

        for (int idx = tid; idx < nrows * 2 * H; idx += THREADS) {
            int r = idx >> 11, k = idx & (2 * H - 1);
            int grow = (r & 3) * H + u0 + (r >> 2);
            float w = (k < H) ? Wih1[(size_t)grow * H + k]
                              : Whh1[(size_t)grow * H + (k - H)];
            sw[idx] = __float2half_rn(w);
        }
        for (int r = tid; r < nrows; r += THREADS) {
            int grow = (r & 3) * H + u0 + (r >> 2);
            sb[r] = bih1[grow] + bhh1[grow];
        }
        for (int u = tid; u < nu; u += THREADS) sc[u] = cell[H + u0 + u];
        __syncthreads();

        for (int t = 0; t < T_STEPS; ++t) {
            if (tid == 0) {
                unsigned needA = (unsigned)(NA * (t + 1));  // h0(t) published
                unsigned needB = (unsigned)(NB * t);        // h1(t-1) published
                while (ld_acquire(&g_cntA) < needA) {}
                while (ld_acquire(&g_cntB) < needB) {}
            }
            __syncthreads();

            const unsigned* h0src = (const unsigned*)(g_Hh0 + (size_t)(t + 1) * H);
            const unsigned* h1src = (const unsigned*)(g_Hh1 + (size_t)t * H);
            shb2[tid]       = ldcg_u32(&h0src[tid]);   // 512 uint
            shb2[512 + tid] = ldcg_u32(&h1src[tid]);   // 512 uint
            __syncthreads();

            uint4 hq[8];
#pragma unroll
            for (int j = 0; j < 8; ++j)
                hq[j] = ((const uint4*)shb2)[j * 32 + lane];

            for (int r = warp; r < nrows; r += 16) {
                const uint4* wq = (const uint4*)(sw + (size_t)r * 2 * H);
                __half2 acc[8];
#pragma unroll
                for (int q = 0; q < 8; ++q) acc[q] = __float2half2_rn(0.f);
#pragma unroll
                for (int j = 0; j < 8; ++j)
                    mac_granule(wq[j * 32 + lane], hq[j], acc + (j & 1) * 4);
                float s = acc8_to_float(acc);
#pragma unroll
                for (int o = 16; o > 0; o >>= 1)
                    s += __shfl_xor_sync(0xffffffffu, s, o);
                if (lane == 0) sg[r] = s + sb[r];
            }
            __syncthreads();

            if (tid < nu) {
                float vi = sg[tid * 4 + 0], vf = sg[tid * 4 + 1];
                float vg = sg[tid * 4 + 2], vo = sg[tid * 4 + 3];
                float ii = 1.f / (1.f + expf(-vi));
                float ff = 1.f / (1.f + expf(-vf));
                float gg = tanhf(vg);
                float oo = 1.f / (1.f + expf(-vo));
                float c  = ff * sc[tid] + ii * gg;
                sc[tid]  = c;
                float h  = oo * tanhf(c);
                stcg_u16(&g_Hh1[(size_t)(t + 1) * H + u0 + tid],
                         __half_as_ushort(__float2half_rn(h)));
                out[(size_t)t * H + u0 + tid] = fmaxf(h, 0.f);
                if (t == T_STEPS - 1 && write_state) {
                    out[BASE_OUT + H + u0 + tid]     = h;   // hf layer 1
                    out[BASE_OUT + 3 * H + u0 + tid] = c;   // cf layer 1
                }
            }
            __syncthreads();
            if (tid == 0) red_release_add1(&g_cntB);
        }
    }
}

// ---------------------------------------------------------------------------
extern "C" void kernel_launch(void* const* d_in, const int* in_sizes, int n_in,
                              void* d_out, int out_size) {
    const float *x = 0, *hidden = 0, *cell = 0, *ip_emb = 0, *port_emb = 0;
    const float *Wih0 = 0, *Whh0 = 0, *bih0 = 0, *bhh0 = 0;
    const float *Wih1 = 0, *Whh1 = 0, *bih1 = 0, *bhh1 = 0;
    const int *ip = 0, *port = 0;

    const float* big[3]  = {0, 0, 0};    int nbig  = 0;
    const float* bias[4] = {0, 0, 0, 0}; int nbias = 0;
    const float* st2[2]  = {0, 0};       int nst2  = 0;

    for (int i = 0; i < n_in; ++i) {
        switch (in_sizes[i]) {
            case 69632:   x        = (const float*)d_in[i]; break;
            case 32768:   ip       = (const int*)  d_in[i]; break;
            case 8192:    port     = (const int*)  d_in[i]; break;
            case 256:     ip_emb   = (const float*)d_in[i]; break;
            case 280000:  port_emb = (const float*)d_in[i]; break;
            case 135168:  Wih0     = (const float*)d_in[i]; break;
            case 4194304: if (nbig  < 3) big[nbig++]   = (const float*)d_in[i]; break;
            case 4096:    if (nbias < 4) bias[nbias++] = (const float*)d_in[i]; break;
            case 2048:    if (nst2  < 2) st2[nst2++]   = (const float*)d_in[i]; break;
            default: break;
        }
    }
    if (nbig == 3 && nbias == 4 && nst2 == 2 && x && ip && port &&
        ip_emb && port_emb && Wih0) {
        Whh0 = big[0]; Wih1 = big[1]; Whh1 = big[2];
        bih0 = bias[0]; bhh0 = bias[1]; bih1 = bias[2]; bhh1 = bias[3];
        hidden = st2[0]; cell = st2[1];
    } else {
        x        = (const float*)d_in[0];
        ip       = (const int*)  d_in[1];
        port     = (const int*)  d_in[2];
        hidden   = (const float*)d_in[3];
        cell     = (const float*)d_in[4];
        ip_emb   = (const float*)d_in[5];
        port_emb = (const float*)d_in[6];
        Wih0     = (const float*)d_in[7];
        Whh0     = (const float*)d_in[8];
        bih0     = (const float*)d_in[9];
        bhh0     = (const float*)d_in[10];
        Wih1     = (const float*)d_in[11];
        Whh1     = (const float*)d_in[12];
        bih1     = (const float*)d_in[13];
        bhh1     = (const float*)d_in[14];
    }
    float* out = (float*)d_out;
    int write_state = (out_size >= (int)(T_STEPS * H + 4 * H)) ? 1 : 0;

    cudaFuncSetAttribute(lstm_kernel,
                         cudaFuncAttributeMaxDynamicSharedMemorySize,
                         SMEM_BYTES);

    init_kernel<<<1, 1024>>>(hidden);
    g0_kernel<<<T_STEPS / 8, 256>>>(x, ip, port, ip_emb, port_emb,
                                    Wih0, bih0, bhh0);
    lstm_kernel<<<GRID, THREADS, SMEM_BYTES>>>(Whh0, Wih1, Whh1,
                                               bih1, bhh1, cell, out,
                                               write_state);
}

// round 6
// speedup vs baseline: 2.0055x; 1.2438x over previous
#include <cuda_runtime.h>
#include <cuda_fp16.h>
#include <math.h>

// ---------------------------------------------------------------------------
// 2-layer LSTM, H=1024, T=4096 sequential steps.
//   g0_kernel : precompute G0[t] = W_ih0 @ xin[t] + b_ih0 + b_hh0 (parallel).
//   lstm_kernel: ONE persistent kernel, 143 co-resident CTAs.
//     CTAs 0..48  : layer-0 units, W_hh0 fp16 in SMEM.
//     CTAs 49..142: layer-1 units, [W_ih1|W_hh1] fp16 in SMEM.
// ROUND-6:
//   * BANKED release counters (8 banks x 256B stride per layer) — kills the
//     ~27cyc/op same-address L2 atomic serialization (94 REDs = ~2500cyc/step
//     on the critical path). Poll reads all banks in parallel (warp 0).
//   * G0 slice prefetched into SMEM by warps 1-3 BEFORE the poll — removes
//     the ~600cyc DRAM load from each row's reduce tail.
//   * HADD2 tree (8 accs -> 1) before the fp32 shuffle reduce.
// ---------------------------------------------------------------------------

#define H        1024
#define T_STEPS  4096
#define GATES    4096
#define NA       49
#define NUA      21
#define NB       94
#define NUB      11
#define GRID     (NA + NB)   // 143
#define THREADS  512
#define BASE_OUT ((size_t)T_STEPS * H)
#define NBANKS   8

// ---- shared memory layout (byte offsets; sized to the max CTA) ----
#define A_W_BYTES (NUA * 4 * H * 2)            // 172032 fp16 weight rows
#define A_HB_OFF  (A_W_BYTES)                  // 1024 halves staged h0
#define A_SG_OFF  (A_HB_OFF + H * 2)
#define A_SC_OFF  (A_SG_OFF + NUA * 4 * 4)
#define A_G0_OFF  (A_SC_OFF + NUA * 4)
#define A_TOTAL   (A_G0_OFF + NUA * 4 * 4)

#define B_W_BYTES (NUB * 4 * 2 * H * 2)        // 180224
#define B_HB_OFF  (B_W_BYTES)                  // 2048 halves [h0(t) ; h1(t-1)]
#define B_SG_OFF  (B_HB_OFF + 2 * H * 2)
#define B_SC_OFF  (B_SG_OFF + NUB * 4 * 4)
#define B_SB_OFF  (B_SC_OFF + NUB * 4)
#define B_TOTAL   (B_SB_OFF + NUB * 4 * 4)

#define SMEM_BYTES (B_TOTAL > A_TOTAL ? B_TOTAL : A_TOTAL)

// ---- device-global scratch ----
__device__ float          g_G0[(size_t)T_STEPS * GATES];        // 64 MB
__device__ unsigned short g_Hh0[(size_t)(T_STEPS + 1) * H];     // h0 history fp16
__device__ unsigned short g_Hh1[(size_t)(T_STEPS + 1) * H];     // h1 history fp16
__device__ unsigned       g_cntA_b[NBANKS * 64];                // 256B-stride banks
__device__ unsigned       g_cntB_b[NBANKS * 64];

__device__ __forceinline__ unsigned ld_acquire(const unsigned* p) {
    unsigned v;
    asm volatile("ld.acquire.gpu.global.u32 %0, [%1];"
                 : "=r"(v) : "l"(p) : "memory");
    return v;
}
__device__ __forceinline__ void red_release_add1(unsigned* p) {
    asm volatile("red.release.gpu.global.add.u32 [%0], %1;"
                 :: "l"(p), "r"(1u) : "memory");
}
__device__ __forceinline__ unsigned ldcg_u32(const unsigned* p) {
    unsigned v;
    asm volatile("ld.global.cg.u32 %0, [%1];" : "=r"(v) : "l"(p));
    return v;
}
__device__ __forceinline__ void stcg_u16(unsigned short* p, unsigned short v) {
    asm volatile("st.global.cg.u16 [%0], %1;" :: "l"(p), "h"(v));
}

// full-warp poll: sum of 8 banks >= target (lanes 0..7 load, shfl-sum)
__device__ __forceinline__ void wait_banks(const unsigned* banks,
                                           unsigned target) {
    const int lane = threadIdx.x & 31;
    for (;;) {
        unsigned v = (lane < NBANKS) ? ld_acquire(&banks[lane << 6]) : 0u;
        v += __shfl_xor_sync(0xffffffffu, v, 1);
        v += __shfl_xor_sync(0xffffffffu, v, 2);
        v += __shfl_xor_sync(0xffffffffu, v, 4);
        v  = __shfl_sync(0xffffffffu, v, 0);
        if (v >= target) return;
    }
}

// 4 HFMA2 on a 16B weight granule against a 16B h granule
__device__ __forceinline__ void mac_granule(const uint4& wq, const uint4& hq,
                                            __half2* acc) {
    acc[0] = __hfma2(*(const __half2*)&wq.x, *(const __half2*)&hq.x, acc[0]);
    acc[1] = __hfma2(*(const __half2*)&wq.y, *(const __half2*)&hq.y, acc[1]);
    acc[2] = __hfma2(*(const __half2*)&wq.z, *(const __half2*)&hq.z, acc[2]);
    acc[3] = __hfma2(*(const __half2*)&wq.w, *(const __half2*)&hq.w, acc[3]);
}

// HADD2 tree 8 -> 1, single conversion, caller does fp32 shfl reduce
__device__ __forceinline__ float acc8_reduce(__half2* acc) {
    acc[0] = __hadd2(acc[0], acc[4]);
    acc[1] = __hadd2(acc[1], acc[5]);
    acc[2] = __hadd2(acc[2], acc[6]);
    acc[3] = __hadd2(acc[3], acc[7]);
    acc[0] = __hadd2(acc[0], acc[2]);
    acc[1] = __hadd2(acc[1], acc[3]);
    acc[0] = __hadd2(acc[0], acc[1]);
    float2 f = __half22float2(acc[0]);
    return f.x + f.y;
}

// ---------------------------------------------------------------------------
__global__ void init_kernel(const float* __restrict__ hidden) {
    int u = threadIdx.x;
    if (u < H) {
        g_Hh0[u] = __half_as_ushort(__float2half_rn(hidden[u]));
        g_Hh1[u] = __half_as_ushort(__float2half_rn(hidden[H + u]));
    }
    if (u < NBANKS * 64) { g_cntA_b[u] = 0u; g_cntB_b[u] = 0u; }
}

// ---------------------------------------------------------------------------
__global__ void g0_kernel(const float* __restrict__ x,
                          const int*   __restrict__ ip,
                          const int*   __restrict__ port,
                          const float* __restrict__ ip_emb,
                          const float* __restrict__ port_emb,
                          const float* __restrict__ Wih0,
                          const float* __restrict__ bih0,
                          const float* __restrict__ bhh0) {
    __shared__ float sxin[8][33];
    const int t0  = blockIdx.x * 8;
    const int tid = threadIdx.x;

    for (int idx = tid; idx < 8 * 33; idx += 256) {
        int tt = idx / 33, k = idx - tt * 33;
        int t = t0 + tt;
        float v;
        if (k < 17)      v = x[t * 17 + k];
        else if (k < 25) v = ip_emb[ip[t * 8 + (k - 17)]];
        else {
            int s = (k - 25) >> 2, e = (k - 25) & 3;
            v = port_emb[port[t * 2 + s] * 4 + e];
        }
        sxin[tt][k] = v;
    }
    __syncthreads();

    for (int j = tid; j < GATES; j += 256) {
        float w[33];
#pragma unroll
        for (int k = 0; k < 33; ++k) w[k] = __ldg(&Wih0[j * 33 + k]);
        float bias = __ldg(&bih0[j]) + __ldg(&bhh0[j]);
#pragma unroll
        for (int tt = 0; tt < 8; ++tt) {
            float acc = bias;
#pragma unroll
            for (int k = 0; k < 33; ++k) acc = fmaf(w[k], sxin[tt][k], acc);
            g_G0[(size_t)(t0 + tt) * GATES + j] = acc;
        }
    }
}

// ---------------------------------------------------------------------------
__global__ __launch_bounds__(THREADS, 1)
void lstm_kernel(const float* __restrict__ Whh0,
                 const float* __restrict__ Wih1,
                 const float* __restrict__ Whh1,
                 const float* __restrict__ bih1,
                 const float* __restrict__ bhh1,
                 const float* __restrict__ cell,
                 float* __restrict__ out,
                 int write_state) {
    extern __shared__ char smem[];
    const int tid  = threadIdx.x;
    const int lane = tid & 31;
    const int warp = tid >> 5;
    const int cta  = blockIdx.x;

    if (cta < NA) {
        // =========================== layer 0 ===========================
        const int u0 = cta * NUA;
        const int nu = min(NUA, H - u0);
        __half*   sw   = (__half*)smem;
        unsigned* shb2 = (unsigned*)(smem + A_HB_OFF);
        float*    sg   = (float*)(smem + A_SG_OFF);
        float*    sc   = (float*)(smem + A_SC_OFF);
        float*    sg0  = (float*)(smem + A_G0_OFF);
        const int nrows = 4 * nu;

        for (int idx = tid; idx < nrows * H; idx += THREADS) {
            int r = idx >> 10, k = idx & (H - 1);
            int grow = (r & 3) * H + u0 + (r >> 2);
            sw[idx] = __float2half_rn(Whh0[(size_t)grow * H + k]);
        }
        for (int u = tid; u < nu; u += THREADS) sc[u] = cell[u0 + u];
        __syncthreads();

        for (int t = 0; t < T_STEPS; ++t) {
            // G0 prefetch by warps 1-3 (independent data); warp 0 polls now
            if (tid >= 32 && tid < 32 + nrows) {
                int r = tid - 32;
                int grow = (r & 3) * H + u0 + (r >> 2);
                sg0[r] = __ldg(&g_G0[(size_t)t * GATES + grow]);
            }
            if (warp == 0) wait_banks(g_cntA_b, (unsigned)(NA * t));
            __syncthreads();

            const unsigned* hsrc = (const unsigned*)(g_Hh0 + (size_t)t * H);
            shb2[tid] = ldcg_u32(&hsrc[tid]);   // THREADS==512 exactly
            __syncthreads();

            uint4 hq[4];
#pragma unroll
            for (int j = 0; j < 4; ++j)
                hq[j] = ((const uint4*)shb2)[j * 32 + lane];

            for (int r = warp; r < nrows; r += 16) {
                const uint4* wq = (const uint4*)(sw + (size_t)r * H);
                __half2 acc[8];
#pragma unroll
                for (int q = 0; q < 8; ++q) acc[q] = __float2half2_rn(0.f);
#pragma unroll
                for (int j = 0; j < 4; ++j)
                    mac_granule(wq[j * 32 + lane], hq[j], acc + (j & 1) * 4);
                float s = acc8_reduce(acc);
#pragma unroll
                for (int o = 16; o > 0; o >>= 1)
                    s += __shfl_xor_sync(0xffffffffu, s, o);
                if (lane == 0) sg[r] = s + sg0[r];
            }
            __syncthreads();

            if (tid < nu) {
                float vi = sg[tid * 4 + 0], vf = sg[tid * 4 + 1];
                float vg = sg[tid * 4 + 2], vo = sg[tid * 4 + 3];
                float ii = 1.f / (1.f + expf(-vi));
                float ff = 1.f / (1.f + expf(-vf));
                float gg = tanhf(vg);
                float oo = 1.f / (1.f + expf(-vo));
                float c  = ff * sc[tid] + ii * gg;
                sc[tid]  = c;
                float h  = oo * tanhf(c);
                stcg_u16(&g_Hh0[(size_t)(t + 1) * H + u0 + tid],
                         __half_as_ushort(__float2half_rn(h)));
                if (t == T_STEPS - 1 && write_state) {
                    out[BASE_OUT + u0 + tid]         = h;   // hf layer 0
                    out[BASE_OUT + 2 * H + u0 + tid] = c;   // cf layer 0
                }
            }
            __syncthreads();
            if (tid == 0) red_release_add1(&g_cntA_b[(cta & (NBANKS - 1)) << 6]);
        }
    } else {
        // =========================== layer 1 ===========================
        const int b  = cta - NA;
        const int u0 = b * NUB;
        const int nu = min(NUB, H - u0);
        __half*   sw   = (__half*)smem;
        unsigned* shb2 = (unsigned*)(smem + B_HB_OFF);
        float*    sg   = (float*)(smem + B_SG_OFF);
        float*    sc   = (float*)(smem + B_SC_OFF);
        float*    sb   = (float*)(smem + B_SB_OFF);
        const int nrows = 4 * nu;

        for (int idx = tid; idx < nrows * 2 * H; idx += THREADS) {
            int r = idx >> 11, k = idx & (2 * H - 1);
            int grow = (r & 3) * H + u0 + (r >> 2);
            float w = (k < H) ? Wih1[(size_t)grow * H + k]
                              : Whh1[(size_t)grow * H + (k - H)];
            sw[idx] = __float2half_rn(w);
        }
        for (int r = tid; r < nrows; r += THREADS) {
            int grow = (r & 3) * H + u0 + (r >> 2);
            sb[r] = bih1[grow] + bhh1[grow];
        }
        for (int u = tid; u < nu; u += THREADS) sc[u] = cell[H + u0 + u];
        __syncthreads();

        for (int t = 0; t < T_STEPS; ++t) {
            if (warp == 0) {
                wait_banks(g_cntA_b, (unsigned)(NA * (t + 1)));  // h0(t) ready
                wait_banks(g_cntB_b, (unsigned)(NB * t));        // h1(t-1) ready
            }
            __syncthreads();

            const unsigned* h0src = (const unsigned*)(g_Hh0 + (size_t)(t + 1) * H);
            const unsigned* h1src = (const unsigned*)(g_Hh1 + (size_t)t * H);
            shb2[tid]       = ldcg_u32(&h0src[tid]);
            shb2[512 + tid] = ldcg_u32(&h1src[tid]);
            __syncthreads();

            uint4 hq[8];
#pragma unroll
            for (int j = 0; j < 8; ++j)
                hq[j] = ((const uint4*)shb2)[j * 32 + lane];

            for (int r = warp; r < nrows; r += 16) {
                const uint4* wq = (const uint4*)(sw + (size_t)r * 2 * H);
                __half2 acc[8];
#pragma unroll
                for (int q = 0; q < 8; ++q) acc[q] = __float2half2_rn(0.f);
#pragma unroll
                for (int j = 0; j < 8; ++j)
                    mac_granule(wq[j * 32 + lane], hq[j], acc + (j & 1) * 4);
                float s = acc8_reduce(acc);
#pragma unroll
                for (int o = 16; o > 0; o >>= 1)
                    s += __shfl_xor_sync(0xffffffffu, s, o);
                if (lane == 0) sg[r] = s + sb[r];
            }
            __syncthreads();

            if (tid < nu) {
                float vi = sg[tid * 4 + 0], vf = sg[tid * 4 + 1];
                float vg = sg[tid * 4 + 2], vo = sg[tid * 4 + 3];
                float ii = 1.f / (1.f + expf(-vi));
                float ff = 1.f / (1.f + expf(-vf));
                float gg = tanhf(vg);
                float oo = 1.f / (1.f + expf(-vo));
                float c  = ff * sc[tid] + ii * gg;
                sc[tid]  = c;
                float h  = oo * tanhf(c);
                stcg_u16(&g_Hh1[(size_t)(t + 1) * H + u0 + tid],
                         __half_as_ushort(__float2half_rn(h)));
                out[(size_t)t * H + u0 + tid] = fmaxf(h, 0.f);
                if (t == T_STEPS - 1 && write_state) {
                    out[BASE_OUT + H + u0 + tid]     = h;   // hf layer 1
                    out[BASE_OUT + 3 * H + u0 + tid] = c;   // cf layer 1
                }
            }
            __syncthreads();
            if (tid == 0) red_release_add1(&g_cntB_b[(cta & (NBANKS - 1)) << 6]);
        }
    }
}

// ---------------------------------------------------------------------------
extern "C" void kernel_launch(void* const* d_in, const int* in_sizes, int n_in,
                              void* d_out, int out_size) {
    const float *x = 0, *hidden = 0, *cell = 0, *ip_emb = 0, *port_emb = 0;
    const float *Wih0 = 0, *Whh0 = 0, *bih0 = 0, *bhh0 = 0;
    const float *Wih1 = 0, *Whh1 = 0, *bih1 = 0, *bhh1 = 0;
    const int *ip = 0, *port = 0;

    const float* big[3]  = {0, 0, 0};    int nbig  = 0;
    const float* bias[4] = {0, 0, 0, 0}; int nbias = 0;
    const float* st2[2]  = {0, 0};       int nst2  = 0;

    for (int i = 0; i < n_in; ++i) {
        switch (in_sizes[i]) {
            case 69632:   x        = (const float*)d_in[i]; break;
            case 32768:   ip       = (const int*)  d_in[i]; break;
            case 8192:    port     = (const int*)  d_in[i]; break;
            case 256:     ip_emb   = (const float*)d_in[i]; break;
            case 280000:  port_emb = (const float*)d_in[i]; break;
            case 135168:  Wih0     = (const float*)d_in[i]; break;
            case 4194304: if (nbig  < 3) big[nbig++]   = (const float*)d_in[i]; break;
            case 4096:    if (nbias < 4) bias[nbias++] = (const float*)d_in[i]; break;
            case 2048:    if (nst2  < 2) st2[nst2++]   = (const float*)d_in[i]; break;
            default: break;
        }
    }
    if (nbig == 3 && nbias == 4 && nst2 == 2 && x && ip && port &&
        ip_emb && port_emb && Wih0) {
        Whh0 = big[0]; Wih1 = big[1]; Whh1 = big[2];
        bih0 = bias[0]; bhh0 = bias[1]; bih1 = bias[2]; bhh1 = bias[3];
        hidden = st2[0]; cell = st2[1];
    } else {
        x        = (const float*)d_in[0];
        ip       = (const int*)  d_in[1];
        port     = (const int*)  d_in[2];
        hidden   = (const float*)d_in[3];
        cell     = (const float*)d_in[4];
        ip_emb   = (const float*)d_in[5];
        port_emb = (const float*)d_in[6];
        Wih0     = (const float*)d_in[7];
        Whh0     = (const float*)d_in[8];
        bih0     = (const float*)d_in[9];
        bhh0     = (const float*)d_in[10];
        Wih1     = (const float*)d_in[11];
        Whh1     = (const float*)d_in[12];
        bih1     = (const float*)d_in[13];
        bhh1     = (const float*)d_in[14];
    }
    float* out = (float*)d_out;
    int write_state = (out_size >= (int)(T_STEPS * H + 4 * H)) ? 1 : 0;

    cudaFuncSetAttribute(lstm_kernel,
                         cudaFuncAttributeMaxDynamicSharedMemorySize,
                         SMEM_BYTES);

    init_kernel<<<1, 1024>>>(hidden);
    g0_kernel<<<T_STEPS / 8, 256>>>(x, ip, port, ip_emb, port_emb,
                                    Wih0, bih0, bhh0);
    lstm_kernel<<<GRID, THREADS, SMEM_BYTES>>>(Whh0, Wih1, Whh1,
                                               bih1, bhh1, cell, out,
                                               write_state);
}

// round 7
// speedup vs baseline: 2.2416x; 1.1177x over previous
#include <cuda_runtime.h>
#include <cuda_fp16.h>
#include <math.h>

// ---------------------------------------------------------------------------
// 2-layer LSTM, H=1024, T=4096 sequential steps. Persistent kernel, 146 CTAs.
//   CTAs 0..51  (A): layer-0, W_hh0 held in REGISTERS (80 uint4/lane max).
//   CTAs 52..145(B): layer-1, [W_ih1|W_hh1] fp16 in SMEM, 2-phase compute:
//     phase1 = W_ih1 @ h0(t) (cntA always ready: A free-runs ahead),
//     phase2 = W_hh1 @ h1(t-1) after cntB poll; partials live in regs.
// ROUND-7: register-resident A weights (kills 1350cyc LDS floor), B phase
//   split (hides one 600cyc poll), __expf-based activations (kills ~400cyc
//   libm tail). Banked counters + monotonic h history from rounds 4-6.
// ---------------------------------------------------------------------------

#define H        1024
#define T_STEPS  4096
#define GATES    4096
#define NA       52          // layer-0 CTAs
#define NUA      20          // units per A CTA (last CTA ragged: 4)
#define NB       94          // layer-1 CTAs
#define NUB      11          // units per B CTA (last ragged: 1)
#define GRID     (NA + NB)   // 146
#define THREADS  512
#define BASE_OUT ((size_t)T_STEPS * H)
#define NBANKS   8

// ---- B shared memory layout ----
#define B_W_BYTES (NUB * 4 * 2 * H * 2)        // 180224
#define B_HB_OFF  (B_W_BYTES)                  // 1024 u32 = 2048 halves
#define B_SG_OFF  (B_HB_OFF + 2 * H * 2)
#define B_SC_OFF  (B_SG_OFF + NUB * 4 * 4)
#define B_SB_OFF  (B_SC_OFF + NUB * 4)
#define B_TOTAL   (B_SB_OFF + NUB * 4 * 4)
// ---- A shared memory layout (small; weights live in regs) ----
#define A_HB_OFF  0                            // 512 u32 staged h0
#define A_SG_OFF  (2048)
#define A_SC_OFF  (A_SG_OFF + NUA * 4 * 4)
#define A_G0_OFF  (A_SC_OFF + NUA * 4)
#define A_TOTAL   (A_G0_OFF + NUA * 4 * 4)

#define SMEM_BYTES (B_TOTAL)

// ---- device-global scratch ----
__device__ float          g_G0[(size_t)T_STEPS * GATES];        // 64 MB
__device__ unsigned short g_Hh0[(size_t)(T_STEPS + 1) * H];     // h0 history fp16
__device__ unsigned short g_Hh1[(size_t)(T_STEPS + 1) * H];     // h1 history fp16
__device__ unsigned       g_cntA_b[NBANKS * 64];
__device__ unsigned       g_cntB_b[NBANKS * 64];

__device__ __forceinline__ unsigned ld_acquire(const unsigned* p) {
    unsigned v;
    asm volatile("ld.acquire.gpu.global.u32 %0, [%1];"
                 : "=r"(v) : "l"(p) : "memory");
    return v;
}
__device__ __forceinline__ void red_release_add1(unsigned* p) {
    asm volatile("red.release.gpu.global.add.u32 [%0], %1;"
                 :: "l"(p), "r"(1u) : "memory");
}
__device__ __forceinline__ unsigned ldcg_u32(const unsigned* p) {
    unsigned v;
    asm volatile("ld.global.cg.u32 %0, [%1];" : "=r"(v) : "l"(p));
    return v;
}
__device__ __forceinline__ void stcg_u16(unsigned short* p, unsigned short v) {
    asm volatile("st.global.cg.u16 [%0], %1;" :: "l"(p), "h"(v));
}

// full-warp poll: sum of 8 banks >= target
__device__ __forceinline__ void wait_banks(const unsigned* banks,
                                           unsigned target) {
    const int lane = threadIdx.x & 31;
    for (;;) {
        unsigned v = (lane < NBANKS) ? ld_acquire(&banks[lane << 6]) : 0u;
        v += __shfl_xor_sync(0xffffffffu, v, 1);
        v += __shfl_xor_sync(0xffffffffu, v, 2);
        v += __shfl_xor_sync(0xffffffffu, v, 4);
        v  = __shfl_sync(0xffffffffu, v, 0);
        if (v >= target) return;
    }
}

// 4 HFMA2 on a 16B weight granule vs 16B h granule into 4 accs
__device__ __forceinline__ void mac_granule4(const uint4& wq, const uint4& hq,
                                             __half2* acc) {
    acc[0] = __hfma2(*(const __half2*)&wq.x, *(const __half2*)&hq.x, acc[0]);
    acc[1] = __hfma2(*(const __half2*)&wq.y, *(const __half2*)&hq.y, acc[1]);
    acc[2] = __hfma2(*(const __half2*)&wq.z, *(const __half2*)&hq.z, acc[2]);
    acc[3] = __hfma2(*(const __half2*)&wq.w, *(const __half2*)&hq.w, acc[3]);
}

__device__ __forceinline__ float acc4_reduce(__half2* acc) {
    acc[0] = __hadd2(acc[0], acc[2]);
    acc[1] = __hadd2(acc[1], acc[3]);
    acc[0] = __hadd2(acc[0], acc[1]);
    float2 f = __half22float2(acc[0]);
    return f.x + f.y;
}
__device__ __forceinline__ float acc8_reduce(__half2* acc) {
    acc[0] = __hadd2(acc[0], acc[4]);
    acc[1] = __hadd2(acc[1], acc[5]);
    acc[2] = __hadd2(acc[2], acc[6]);
    acc[3] = __hadd2(acc[3], acc[7]);
    acc[0] = __hadd2(acc[0], acc[2]);
    acc[1] = __hadd2(acc[1], acc[3]);
    acc[0] = __hadd2(acc[0], acc[1]);
    float2 f = __half22float2(acc[0]);
    return f.x + f.y;
}

// fast activations (EX2/RCP based, safe saturation)
__device__ __forceinline__ float fsig(float x) {
    return __fdividef(1.f, 1.f + __expf(-x));
}
__device__ __forceinline__ float ftanh(float x) {
    return 1.f - __fdividef(2.f, __expf(2.f * x) + 1.f);
}

__device__ __forceinline__ unsigned pack_h2(float a, float b) {
    __half2 h = __halves2half2(__float2half_rn(a), __float2half_rn(b));
    return *(unsigned*)&h;
}

// ---------------------------------------------------------------------------
__global__ void init_kernel(const float* __restrict__ hidden) {
    int u = threadIdx.x;
    if (u < H) {
        g_Hh0[u] = __half_as_ushort(__float2half_rn(hidden[u]));
        g_Hh1[u] = __half_as_ushort(__float2half_rn(hidden[H + u]));
    }
    if (u < NBANKS * 64) { g_cntA_b[u] = 0u; g_cntB_b[u] = 0u; }
}

// ---------------------------------------------------------------------------
__global__ void g0_kernel(const float* __restrict__ x,
                          const int*   __restrict__ ip,
                          const int*   __restrict__ port,
                          const float* __restrict__ ip_emb,
                          const float* __restrict__ port_emb,
                          const float* __restrict__ Wih0,
                          const float* __restrict__ bih0,
                          const float* __restrict__ bhh0) {
    __shared__ float sxin[8][33];
    const int t0  = blockIdx.x * 8;
    const int tid = threadIdx.x;

    for (int idx = tid; idx < 8 * 33; idx += 256) {
        int tt = idx / 33, k = idx - tt * 33;
        int t = t0 + tt;
        float v;
        if (k < 17)      v = x[t * 17 + k];
        else if (k < 25) v = ip_emb[ip[t * 8 + (k - 17)]];
        else {
            int s = (k - 25) >> 2, e = (k - 25) & 3;
            v = port_emb[port[t * 2 + s] * 4 + e];
        }
        sxin[tt][k] = v;
    }
    __syncthreads();

    for (int j = tid; j < GATES; j += 256) {
        float w[33];
#pragma unroll
        for (int k = 0; k < 33; ++k) w[k] = __ldg(&Wih0[j * 33 + k]);
        float bias = __ldg(&bih0[j]) + __ldg(&bhh0[j]);
#pragma unroll
        for (int tt = 0; tt < 8; ++tt) {
            float acc = bias;
#pragma unroll
            for (int k = 0; k < 33; ++k) acc = fmaf(w[k], sxin[tt][k], acc);
            g_G0[(size_t)(t0 + tt) * GATES + j] = acc;
        }
    }
}

// ---------------------------------------------------------------------------
__global__ __launch_bounds__(THREADS, 1)
void lstm_kernel(const float* __restrict__ Whh0,
                 const float* __restrict__ Wih1,
                 const float* __restrict__ Whh1,
                 const float* __restrict__ bih1,
                 const float* __restrict__ bhh1,
                 const float* __restrict__ cell,
                 float* __restrict__ out,
                 int write_state) {
    extern __shared__ char smem[];
    const int tid  = threadIdx.x;
    const int lane = tid & 31;
    const int warp = tid >> 5;
    const int cta  = blockIdx.x;

    if (cta < NA) {
        // ================ layer 0 : weights in REGISTERS =================
        const int u0 = cta * NUA;
        const int nu = min(NUA, H - u0);
        const int nrows = 4 * nu;          // 80 or 16
        const int rpw   = nrows >> 4;      // 5 or 1 (rows per warp)
        unsigned* shb2 = (unsigned*)(smem + A_HB_OFF);
        float*    sg   = (float*)(smem + A_SG_OFF);
        float*    sc   = (float*)(smem + A_SC_OFF);
        float*    sg0  = (float*)(smem + A_G0_OFF);

        // one-time: fp32 -> fp16 weights into registers
        uint4 w[5][4];
#pragma unroll
        for (int q = 0; q < 5; ++q)
#pragma unroll
            for (int g = 0; g < 4; ++g)
                w[q][g] = make_uint4(0u, 0u, 0u, 0u);
#pragma unroll
        for (int q = 0; q < 5; ++q) {
            if (q < rpw) {
                int lr = warp * rpw + q;
                int grow = (lr & 3) * H + u0 + (lr >> 2);
                const float* src = Whh0 + (size_t)grow * H;
#pragma unroll
                for (int g = 0; g < 4; ++g) {
                    int base = (g * 32 + lane) * 8;
                    float4 f0 = *(const float4*)(src + base);
                    float4 f1 = *(const float4*)(src + base + 4);
                    uint4 v;
                    v.x = pack_h2(f0.x, f0.y);
                    v.y = pack_h2(f0.z, f0.w);
                    v.z = pack_h2(f1.x, f1.y);
                    v.w = pack_h2(f1.z, f1.w);
                    w[q][g] = v;
                }
            }
        }
        for (int u = tid; u < nu; u += THREADS) sc[u] = cell[u0 + u];
        __syncthreads();

        for (int t = 0; t < T_STEPS; ++t) {
            // G0 prefetch (warps 1..3) overlaps warp-0 poll
            if (tid >= 32 && tid < 32 + nrows) {
                int r = tid - 32;
                int grow = (r & 3) * H + u0 + (r >> 2);
                sg0[r] = __ldg(&g_G0[(size_t)t * GATES + grow]);
            }
            if (warp == 0) wait_banks(g_cntA_b, (unsigned)(NA * t));
            __syncthreads();

            const unsigned* hsrc = (const unsigned*)(g_Hh0 + (size_t)t * H);
            shb2[tid] = ldcg_u32(&hsrc[tid]);    // THREADS==512 exactly
            __syncthreads();

            uint4 hq[4];
#pragma unroll
            for (int j = 0; j < 4; ++j)
                hq[j] = ((const uint4*)shb2)[j * 32 + lane];

#pragma unroll
            for (int q = 0; q < 5; ++q) {
                if (q < rpw) {
                    __half2 acc[4];
#pragma unroll
                    for (int a = 0; a < 4; ++a) acc[a] = __float2half2_rn(0.f);
#pragma unroll
                    for (int g = 0; g < 4; ++g)
                        mac_granule4(w[q][g], hq[g], acc);
                    float s = acc4_reduce(acc);
#pragma unroll
                    for (int o = 16; o > 0; o >>= 1)
                        s += __shfl_xor_sync(0xffffffffu, s, o);
                    if (lane == 0) {
                        int lr = warp * rpw + q;
                        sg[lr] = s + sg0[lr];
                    }
                }
            }
            __syncthreads();

            if (tid < nu) {
                float ii = fsig(sg[tid * 4 + 0]);
                float ff = fsig(sg[tid * 4 + 1]);
                float gg = ftanh(sg[tid * 4 + 2]);
                float oo = fsig(sg[tid * 4 + 3]);
                float c  = ff * sc[tid] + ii * gg;
                sc[tid]  = c;
                float h  = oo * ftanh(c);
                stcg_u16(&g_Hh0[(size_t)(t + 1) * H + u0 + tid],
                         __half_as_ushort(__float2half_rn(h)));
                if (t == T_STEPS - 1 && write_state) {
                    out[BASE_OUT + u0 + tid]         = h;   // hf layer 0
                    out[BASE_OUT + 2 * H + u0 + tid] = c;   // cf layer 0
                }
            }
            __syncthreads();
            if (tid == 0) red_release_add1(&g_cntA_b[(cta & (NBANKS - 1)) << 6]);
        }
    } else {
        // ================ layer 1 : SMEM weights, 2-phase =================
        const int b  = cta - NA;
        const int u0 = b * NUB;
        const int nu = min(NUB, H - u0);
        __half*   sw   = (__half*)smem;
        unsigned* shb2 = (unsigned*)(smem + B_HB_OFF);
        float*    sg   = (float*)(smem + B_SG_OFF);
        float*    sc   = (float*)(smem + B_SC_OFF);
        float*    sb   = (float*)(smem + B_SB_OFF);
        const int nrows = 4 * nu;

        for (int idx = tid; idx < nrows * 2 * H; idx += THREADS) {
            int r = idx >> 11, k = idx & (2 * H - 1);
            int grow = (r & 3) * H + u0 + (r >> 2);
            float wv = (k < H) ? Wih1[(size_t)grow * H + k]
                               : Whh1[(size_t)grow * H + (k - H)];
            sw[idx] = __float2half_rn(wv);
        }
        for (int r = tid; r < nrows; r += THREADS) {
            int grow = (r & 3) * H + u0 + (r >> 2);
            sb[r] = bih1[grow] + bhh1[grow];
        }
        for (int u = tid; u < nu; u += THREADS) sc[u] = cell[H + u0 + u];
        __syncthreads();

        for (int t = 0; t < T_STEPS; ++t) {
            // ---------- phase 1: W_ih1 @ h0(t)  (cntA usually ahead) ----------
            if (warp == 0) wait_banks(g_cntA_b, (unsigned)(NA * (t + 1)));
            __syncthreads();
            const unsigned* h0src = (const unsigned*)(g_Hh0 + (size_t)(t + 1) * H);
            shb2[tid] = ldcg_u32(&h0src[tid]);
            __syncthreads();

            uint4 hq[4];
#pragma unroll
            for (int j = 0; j < 4; ++j)
                hq[j] = ((const uint4*)shb2)[j * 32 + lane];

            __half2 acc[3][8];
#pragma unroll
            for (int ri = 0; ri < 3; ++ri)
#pragma unroll
                for (int q = 0; q < 8; ++q)
                    acc[ri][q] = __float2half2_rn(0.f);

#pragma unroll
            for (int ri = 0; ri < 3; ++ri) {
                int r = warp + ri * 16;
                if (r < nrows) {
                    const uint4* wq = (const uint4*)(sw + (size_t)r * 2 * H);
#pragma unroll
                    for (int j = 0; j < 4; ++j)
                        mac_granule4(wq[j * 32 + lane], hq[j],
                                     acc[ri] + (j & 1) * 4);
                }
            }

            // ---------- phase 2: W_hh1 @ h1(t-1) ----------
            if (warp == 0) wait_banks(g_cntB_b, (unsigned)(NB * t));
            __syncthreads();
            const unsigned* h1src = (const unsigned*)(g_Hh1 + (size_t)t * H);
            shb2[512 + tid] = ldcg_u32(&h1src[tid]);
            __syncthreads();

#pragma unroll
            for (int j = 0; j < 4; ++j)
                hq[j] = ((const uint4*)shb2)[(4 + j) * 32 + lane];

#pragma unroll
            for (int ri = 0; ri < 3; ++ri) {
                int r = warp + ri * 16;
                if (r < nrows) {
                    const uint4* wq = (const uint4*)(sw + (size_t)r * 2 * H);
#pragma unroll
                    for (int j = 4; j < 8; ++j)
                        mac_granule4(wq[j * 32 + lane], hq[j - 4],
                                     acc[ri] + (j & 1) * 4);
                    float s = acc8_reduce(acc[ri]);
#pragma unroll
                    for (int o = 16; o > 0; o >>= 1)
                        s += __shfl_xor_sync(0xffffffffu, s, o);
                    if (lane == 0) sg[r] = s + sb[r];
                }
            }
            __syncthreads();

            if (tid < nu) {
                float ii = fsig(sg[tid * 4 + 0]);
                float ff = fsig(sg[tid * 4 + 1]);
                float gg = ftanh(sg[tid * 4 + 2]);
                float oo = fsig(sg[tid * 4 + 3]);
                float c  = ff * sc[tid] + ii * gg;
                sc[tid]  = c;
                float h  = oo * ftanh(c);
                stcg_u16(&g_Hh1[(size_t)(t + 1) * H + u0 + tid],
                         __half_as_ushort(__float2half_rn(h)));
                out[(size_t)t * H + u0 + tid] = fmaxf(h, 0.f);
                if (t == T_STEPS - 1 && write_state) {
                    out[BASE_OUT + H + u0 + tid]     = h;   // hf layer 1
                    out[BASE_OUT + 3 * H + u0 + tid] = c;   // cf layer 1
                }
            }
            __syncthreads();
            if (tid == 0) red_release_add1(&g_cntB_b[(cta & (NBANKS - 1)) << 6]);
        }
    }
}

// ---------------------------------------------------------------------------
extern "C" void kernel_launch(void* const* d_in, const int* in_sizes, int n_in,
                              void* d_out, int out_size) {
    const float *x = 0, *hidden = 0, *cell = 0, *ip_emb = 0, *port_emb = 0;
    const float *Wih0 = 0, *Whh0 = 0, *bih0 = 0, *bhh0 = 0;
    const float *Wih1 = 0, *Whh1 = 0, *bih1 = 0, *bhh1 = 0;
    const int *ip = 0, *port = 0;

    const float* big[3]  = {0, 0, 0};    int nbig  = 0;
    const float* bias[4] = {0, 0, 0, 0}; int nbias = 0;
    const float* st2[2]  = {0, 0};       int nst2  = 0;

    for (int i = 0; i < n_in; ++i) {
        switch (in_sizes[i]) {
            case 69632:   x        = (const float*)d_in[i]; break;
            case 32768:   ip       = (const int*)  d_in[i]; break;
            case 8192:    port     = (const int*)  d_in[i]; break;
            case 256:     ip_emb   = (const float*)d_in[i]; break;
            case 280000:  port_emb = (const float*)d_in[i]; break;
            case 135168:  Wih0     = (const float*)d_in[i]; break;
            case 4194304: if (nbig  < 3) big[nbig++]   = (const float*)d_in[i]; break;
            case 4096:    if (nbias < 4) bias[nbias++] = (const float*)d_in[i]; break;
            case 2048:    if (nst2  < 2) st2[nst2++]   = (const float*)d_in[i]; break;
            default: break;
        }
    }
    if (nbig == 3 && nbias == 4 && nst2 == 2 && x && ip && port &&
        ip_emb && port_emb && Wih0) {
        Whh0 = big[0]; Wih1 = big[1]; Whh1 = big[2];
        bih0 = bias[0]; bhh0 = bias[1]; bih1 = bias[2]; bhh1 = bias[3];
        hidden = st2[0]; cell = st2[1];
    } else {
        x        = (const float*)d_in[0];
        ip       = (const int*)  d_in[1];
        port     = (const int*)  d_in[2];
        hidden   = (const float*)d_in[3];
        cell     = (const float*)d_in[4];
        ip_emb   = (const float*)d_in[5];
        port_emb = (const float*)d_in[6];
        Wih0     = (const float*)d_in[7];
        Whh0     = (const float*)d_in[8];
        bih0     = (const float*)d_in[9];
        bhh0     = (const float*)d_in[10];
        Wih1     = (const float*)d_in[11];
        Whh1     = (const float*)d_in[12];
        bih1     = (const float*)d_in[13];
        bhh1     = (const float*)d_in[14];
    }
    float* out = (float*)d_out;
    int write_state = (out_size >= (int)(T_STEPS * H + 4 * H)) ? 1 : 0;

    cudaFuncSetAttribute(lstm_kernel,
                         cudaFuncAttributeMaxDynamicSharedMemorySize,
                         SMEM_BYTES);

    init_kernel<<<1, 1024>>>(hidden);
    g0_kernel<<<T_STEPS / 8, 256>>>(x, ip, port, ip_emb, port_emb,
                                    Wih0, bih0, bhh0);
    lstm_kernel<<<GRID, THREADS, SMEM_BYTES>>>(Whh0, Wih1, Whh1,
                                               bih1, bhh1, cell, out,
                                               write_state);
}

// round 8
// speedup vs baseline: 2.2428x; 1.0005x over previous
#include <cuda_runtime.h>
#include <cuda_fp16.h>
#include <math.h>

// ---------------------------------------------------------------------------
// 2-layer LSTM, H=1024, T=4096 sequential steps. Persistent kernel, 146 CTAs.
//   CTAs 0..51  (A): layer-0, W_hh0 held in REGISTERS (80 uint4/lane max).
//   CTAs 52..145(B): layer-1, [W_ih1|W_hh1] fp16 in SMEM, 2-phase compute:
//     phase1 = W_ih1 @ h0(t) (cntA always ready: A free-runs ahead),
//     phase2 = W_hh1 @ h1(t-1) after cntB poll; partials live in regs.
// ROUND-7: register-resident A weights (kills 1350cyc LDS floor), B phase
//   split (hides one 600cyc poll), __expf-based activations (kills ~400cyc
//   libm tail). Banked counters + monotonic h history from rounds 4-6.
// ---------------------------------------------------------------------------

#define H        1024
#define T_STEPS  4096
#define GATES    4096
#define NA       52          // layer-0 CTAs
#define NUA      20          // units per A CTA (last CTA ragged: 4)
#define NB       94          // layer-1 CTAs
#define NUB      11          // units per B CTA (last ragged: 1)
#define GRID     (NA + NB)   // 146
#define THREADS  512
#define BASE_OUT ((size_t)T_STEPS * H)
#define NBANKS   8

// ---- B shared memory layout ----
#define B_W_BYTES (NUB * 4 * 2 * H * 2)        // 180224
#define B_HB_OFF  (B_W_BYTES)                  // 1024 u32 = 2048 halves
#define B_SG_OFF  (B_HB_OFF + 2 * H * 2)
#define B_SC_OFF  (B_SG_OFF + NUB * 4 * 4)
#define B_SB_OFF  (B_SC_OFF + NUB * 4)
#define B_TOTAL   (B_SB_OFF + NUB * 4 * 4)
// ---- A shared memory layout (small; weights live in regs) ----
#define A_HB_OFF  0                            // 512 u32 staged h0
#define A_SG_OFF  (2048)
#define A_SC_OFF  (A_SG_OFF + NUA * 4 * 4)
#define A_G0_OFF  (A_SC_OFF + NUA * 4)
#define A_TOTAL   (A_G0_OFF + NUA * 4 * 4)

#define SMEM_BYTES (B_TOTAL)

// ---- device-global scratch ----
__device__ float          g_G0[(size_t)T_STEPS * GATES];        // 64 MB
__device__ unsigned short g_Hh0[(size_t)(T_STEPS + 1) * H];     // h0 history fp16
__device__ unsigned short g_Hh1[(size_t)(T_STEPS + 1) * H];     // h1 history fp16
__device__ unsigned       g_cntA_b[NBANKS * 64];
__device__ unsigned       g_cntB_b[NBANKS * 64];

__device__ __forceinline__ unsigned ld_acquire(const unsigned* p) {
    unsigned v;
    asm volatile("ld.acquire.gpu.global.u32 %0, [%1];"
                 : "=r"(v) : "l"(p) : "memory");
    return v;
}
__device__ __forceinline__ void red_release_add1(unsigned* p) {
    asm volatile("red.release.gpu.global.add.u32 [%0], %1;"
                 :: "l"(p), "r"(1u) : "memory");
}
__device__ __forceinline__ unsigned ldcg_u32(const unsigned* p) {
    unsigned v;
    asm volatile("ld.global.cg.u32 %0, [%1];" : "=r"(v) : "l"(p));
    return v;
}
__device__ __forceinline__ void stcg_u16(unsigned short* p, unsigned short v) {
    asm volatile("st.global.cg.u16 [%0], %1;" :: "l"(p), "h"(v));
}

// full-warp poll: sum of 8 banks >= target
__device__ __forceinline__ void wait_banks(const unsigned* banks,
                                           unsigned target) {
    const int lane = threadIdx.x & 31;
    for (;;) {
        unsigned v = (lane < NBANKS) ? ld_acquire(&banks[lane << 6]) : 0u;
        v += __shfl_xor_sync(0xffffffffu, v, 1);
        v += __shfl_xor_sync(0xffffffffu, v, 2);
        v += __shfl_xor_sync(0xffffffffu, v, 4);
        v  = __shfl_sync(0xffffffffu, v, 0);
        if (v >= target) return;
    }
}

// 4 HFMA2 on a 16B weight granule vs 16B h granule into 4 accs
__device__ __forceinline__ void mac_granule4(const uint4& wq, const uint4& hq,
                                             __half2* acc) {
    acc[0] = __hfma2(*(const __half2*)&wq.x, *(const __half2*)&hq.x, acc[0]);
    acc[1] = __hfma2(*(const __half2*)&wq.y, *(const __half2*)&hq.y, acc[1]);
    acc[2] = __hfma2(*(const __half2*)&wq.z, *(const __half2*)&hq.z, acc[2]);
    acc[3] = __hfma2(*(const __half2*)&wq.w, *(const __half2*)&hq.w, acc[3]);
}

__device__ __forceinline__ float acc4_reduce(__half2* acc) {
    acc[0] = __hadd2(acc[0], acc[2]);
    acc[1] = __hadd2(acc[1], acc[3]);
    acc[0] = __hadd2(acc[0], acc[1]);
    float2 f = __half22float2(acc[0]);
    return f.x + f.y;
}
__device__ __forceinline__ float acc8_reduce(__half2* acc) {
    acc[0] = __hadd2(acc[0], acc[4]);
    acc[1] = __hadd2(acc[1], acc[5]);
    acc[2] = __hadd2(acc[2], acc[6]);
    acc[3] = __hadd2(acc[3], acc[7]);
    acc[0] = __hadd2(acc[0], acc[2]);
    acc[1] = __hadd2(acc[1], acc[3]);
    acc[0] = __hadd2(acc[0], acc[1]);
    float2 f = __half22float2(acc[0]);
    return f.x + f.y;
}

// fast activations (EX2/RCP based, safe saturation)
__device__ __forceinline__ float fsig(float x) {
    return __fdividef(1.f, 1.f + __expf(-x));
}
__device__ __forceinline__ float ftanh(float x) {
    return 1.f - __fdividef(2.f, __expf(2.f * x) + 1.f);
}

__device__ __forceinline__ unsigned pack_h2(float a, float b) {
    __half2 h = __halves2half2(__float2half_rn(a), __float2half_rn(b));
    return *(unsigned*)&h;
}

// ---------------------------------------------------------------------------
__global__ void init_kernel(const float* __restrict__ hidden) {
    int u = threadIdx.x;
    if (u < H) {
        g_Hh0[u] = __half_as_ushort(__float2half_rn(hidden[u]));
        g_Hh1[u] = __half_as_ushort(__float2half_rn(hidden[H + u]));
    }
    if (u < NBANKS * 64) { g_cntA_b[u] = 0u; g_cntB_b[u] = 0u; }
}

// ---------------------------------------------------------------------------
__global__ void g0_kernel(const float* __restrict__ x,
                          const int*   __restrict__ ip,
                          const int*   __restrict__ port,
                          const float* __restrict__ ip_emb,
                          const float* __restrict__ port_emb,
                          const float* __restrict__ Wih0,
                          const float* __restrict__ bih0,
                          const float* __restrict__ bhh0) {
    __shared__ float sxin[8][33];
    const int t0  = blockIdx.x * 8;
    const int tid = threadIdx.x;

    for (int idx = tid; idx < 8 * 33; idx += 256) {
        int tt = idx / 33, k = idx - tt * 33;
        int t = t0 + tt;
        float v;
        if (k < 17)      v = x[t * 17 + k];
        else if (k < 25) v = ip_emb[ip[t * 8 + (k - 17)]];
        else {
            int s = (k - 25) >> 2, e = (k - 25) & 3;
            v = port_emb[port[t * 2 + s] * 4 + e];
        }
        sxin[tt][k] = v;
    }
    __syncthreads();

    for (int j = tid; j < GATES; j += 256) {
        float w[33];
#pragma unroll
        for (int k = 0; k < 33; ++k) w[k] = __ldg(&Wih0[j * 33 + k]);
        float bias = __ldg(&bih0[j]) + __ldg(&bhh0[j]);
#pragma unroll
        for (int tt = 0; tt < 8; ++tt) {
            float acc = bias;
#pragma unroll
            for (int k = 0; k < 33; ++k) acc = fmaf(w[k], sxin[tt][k], acc);
            g_G0[(size_t)(t0 + tt) * GATES + j] = acc;
        }
    }
}

// ---------------------------------------------------------------------------
__global__ __launch_bounds__(THREADS, 1)
void lstm_kernel(const float* __restrict__ Whh0,
                 const float* __restrict__ Wih1,
                 const float* __restrict__ Whh1,
                 const float* __restrict__ bih1,
                 const float* __restrict__ bhh1,
                 const float* __restrict__ cell,
                 float* __restrict__ out,
                 int write_state) {
    extern __shared__ char smem[];
    const int tid  = threadIdx.x;
    const int lane = tid & 31;
    const int warp = tid >> 5;
    const int cta  = blockIdx.x;

    if (cta < NA) {
        // ================ layer 0 : weights in REGISTERS =================
        const int u0 = cta * NUA;
        const int nu = min(NUA, H - u0);
        const int nrows = 4 * nu;          // 80 or 16
        const int rpw   = nrows >> 4;      // 5 or 1 (rows per warp)
        unsigned* shb2 = (unsigned*)(smem + A_HB_OFF);
        float*    sg   = (float*)(smem + A_SG_OFF);
        float*    sc   = (float*)(smem + A_SC_OFF);
        float*    sg0  = (float*)(smem + A_G0_OFF);

        // one-time: fp32 -> fp16 weights into registers
        uint4 w[5][4];
#pragma unroll
        for (int q = 0; q < 5; ++q)
#pragma unroll
            for (int g = 0; g < 4; ++g)
                w[q][g] = make_uint4(0u, 0u, 0u, 0u);
#pragma unroll
        for (int q = 0; q < 5; ++q) {
            if (q < rpw) {
                int lr = warp * rpw + q;
                int grow = (lr & 3) * H + u0 + (lr >> 2);
                const float* src = Whh0 + (size_t)grow * H;
#pragma unroll
                for (int g = 0; g < 4; ++g) {
                    int base = (g * 32 + lane) * 8;
                    float4 f0 = *(const float4*)(src + base);
                    float4 f1 = *(const float4*)(src + base + 4);
                    uint4 v;
                    v.x = pack_h2(f0.x, f0.y);
                    v.y = pack_h2(f0.z, f0.w);
                    v.z = pack_h2(f1.x, f1.y);
                    v.w = pack_h2(f1.z, f1.w);
                    w[q][g] = v;
                }
            }
        }
        for (int u = tid; u < nu; u += THREADS) sc[u] = cell[u0 + u];
        __syncthreads();

        for (int t = 0; t < T_STEPS; ++t) {
            // G0 prefetch (warps 1..3) overlaps warp-0 poll
            if (tid >= 32 && tid < 32 + nrows) {
                int r = tid - 32;
                int grow = (r & 3) * H + u0 + (r >> 2);
                sg0[r] = __ldg(&g_G0[(size_t)t * GATES + grow]);
            }
            if (warp == 0) wait_banks(g_cntA_b, (unsigned)(NA * t));
            __syncthreads();

            const unsigned* hsrc = (const unsigned*)(g_Hh0 + (size_t)t * H);
            shb2[tid] = ldcg_u32(&hsrc[tid]);    // THREADS==512 exactly
            __syncthreads();

            uint4 hq[4];
#pragma unroll
            for (int j = 0; j < 4; ++j)
                hq[j] = ((const uint4*)shb2)[j * 32 + lane];

#pragma unroll
            for (int q = 0; q < 5; ++q) {
                if (q < rpw) {
                    __half2 acc[4];
#pragma unroll
                    for (int a = 0; a < 4; ++a) acc[a] = __float2half2_rn(0.f);
#pragma unroll
                    for (int g = 0; g < 4; ++g)
                        mac_granule4(w[q][g], hq[g], acc);
                    float s = acc4_reduce(acc);
#pragma unroll
                    for (int o = 16; o > 0; o >>= 1)
                        s += __shfl_xor_sync(0xffffffffu, s, o);
                    if (lane == 0) {
                        int lr = warp * rpw + q;
                        sg[lr] = s + sg0[lr];
                    }
                }
            }
            __syncthreads();

            if (tid < nu) {
                float ii = fsig(sg[tid * 4 + 0]);
                float ff = fsig(sg[tid * 4 + 1]);
                float gg = ftanh(sg[tid * 4 + 2]);
                float oo = fsig(sg[tid * 4 + 3]);
                float c  = ff * sc[tid] + ii * gg;
                sc[tid]  = c;
                float h  = oo * ftanh(c);
                stcg_u16(&g_Hh0[(size_t)(t + 1) * H + u0 + tid],
                         __half_as_ushort(__float2half_rn(h)));
                if (t == T_STEPS - 1 && write_state) {
                    out[BASE_OUT + u0 + tid]         = h;   // hf layer 0
                    out[BASE_OUT + 2 * H + u0 + tid] = c;   // cf layer 0
                }
            }
            __syncthreads();
            if (tid == 0) red_release_add1(&g_cntA_b[(cta & (NBANKS - 1)) << 6]);
        }
    } else {
        // ================ layer 1 : SMEM weights, 2-phase =================
        const int b  = cta - NA;
        const int u0 = b * NUB;
        const int nu = min(NUB, H - u0);
        __half*   sw   = (__half*)smem;
        unsigned* shb2 = (unsigned*)(smem + B_HB_OFF);
        float*    sg   = (float*)(smem + B_SG_OFF);
        float*    sc   = (float*)(smem + B_SC_OFF);
        float*    sb   = (float*)(smem + B_SB_OFF);
        const int nrows = 4 * nu;

        for (int idx = tid; idx < nrows * 2 * H; idx += THREADS) {
            int r = idx >> 11, k = idx & (2 * H - 1);
            int grow = (r & 3) * H + u0 + (r >> 2);
            float wv = (k < H) ? Wih1[(size_t)grow * H + k]
                               : Whh1[(size_t)grow * H + (k - H)];
            sw[idx] = __float2half_rn(wv);
        }
        for (int r = tid; r < nrows; r += THREADS) {
            int grow = (r & 3) * H + u0 + (r >> 2);
            sb[r] = bih1[grow] + bhh1[grow];
        }
        for (int u = tid; u < nu; u += THREADS) sc[u] = cell[H + u0 + u];
        __syncthreads();

        for (int t = 0; t < T_STEPS; ++t) {
            // ---------- phase 1: W_ih1 @ h0(t)  (cntA usually ahead) ----------
            if (warp == 0) wait_banks(g_cntA_b, (unsigned)(NA * (t + 1)));
            __syncthreads();
            const unsigned* h0src = (const unsigned*)(g_Hh0 + (size_t)(t + 1) * H);
            shb2[tid] = ldcg_u32(&h0src[tid]);
            __syncthreads();

            uint4 hq[4];
#pragma unroll
            for (int j = 0; j < 4; ++j)
                hq[j] = ((const uint4*)shb2)[j * 32 + lane];

            __half2 acc[3][8];
#pragma unroll
            for (int ri = 0; ri < 3; ++ri)
#pragma unroll
                for (int q = 0; q < 8; ++q)
                    acc[ri][q] = __float2half2_rn(0.f);

#pragma unroll
            for (int ri = 0; ri < 3; ++ri) {
                int r = warp + ri * 16;
                if (r < nrows) {
                    const uint4* wq = (const uint4*)(sw + (size_t)r * 2 * H);
#pragma unroll
                    for (int j = 0; j < 4; ++j)
                        mac_granule4(wq[j * 32 + lane], hq[j],
                                     acc[ri] + (j & 1) * 4);
                }
            }

            // ---------- phase 2: W_hh1 @ h1(t-1) ----------
            if (warp == 0) wait_banks(g_cntB_b, (unsigned)(NB * t));
            __syncthreads();
            const unsigned* h1src = (const unsigned*)(g_Hh1 + (size_t)t * H);
            shb2[512 + tid] = ldcg_u32(&h1src[tid]);
            __syncthreads();

#pragma unroll
            for (int j = 0; j < 4; ++j)
                hq[j] = ((const uint4*)shb2)[(4 + j) * 32 + lane];

#pragma unroll
            for (int ri = 0; ri < 3; ++ri) {
                int r = warp + ri * 16;
                if (r < nrows) {
                    const uint4* wq = (const uint4*)(sw + (size_t)r * 2 * H);
#pragma unroll
                    for (int j = 4; j < 8; ++j)
                        mac_granule4(wq[j * 32 + lane], hq[j - 4],
                                     acc[ri] + (j & 1) * 4);
                    float s = acc8_reduce(acc[ri]);
#pragma unroll
                    for (int o = 16; o > 0; o >>= 1)
                        s += __shfl_xor_sync(0xffffffffu, s, o);
                    if (lane == 0) sg[r] = s + sb[r];
                }
            }
            __syncthreads();

            if (tid < nu) {
                float ii = fsig(sg[tid * 4 + 0]);
                float ff = fsig(sg[tid * 4 + 1]);
                float gg = ftanh(sg[tid * 4 + 2]);
                float oo = fsig(sg[tid * 4 + 3]);
                float c  = ff * sc[tid] + ii * gg;
                sc[tid]  = c;
                float h  = oo * ftanh(c);
                stcg_u16(&g_Hh1[(size_t)(t + 1) * H + u0 + tid],
                         __half_as_ushort(__float2half_rn(h)));
                out[(size_t)t * H + u0 + tid] = fmaxf(h, 0.f);
                if (t == T_STEPS - 1 && write_state) {
                    out[BASE_OUT + H + u0 + tid]     = h;   // hf layer 1
                    out[BASE_OUT + 3 * H + u0 + tid] = c;   // cf layer 1
                }
            }
            __syncthreads();
            if (tid == 0) red_release_add1(&g_cntB_b[(cta & (NBANKS - 1)) << 6]);
        }
    }
}

// ---------------------------------------------------------------------------
extern "C" void kernel_launch(void* const* d_in, const int* in_sizes, int n_in,
                              void* d_out, int out_size) {
    const float *x = 0, *hidden = 0, *cell = 0, *ip_emb = 0, *port_emb = 0;
    const float *Wih0 = 0, *Whh0 = 0, *bih0 = 0, *bhh0 = 0;
    const float *Wih1 = 0, *Whh1 = 0, *bih1 = 0, *bhh1 = 0;
    const int *ip = 0, *port = 0;

    const float* big[3]  = {0, 0, 0};    int nbig  = 0;
    const float* bias[4] = {0, 0, 0, 0}; int nbias = 0;
    const float* st2[2]  = {0, 0};       int nst2  = 0;

    for (int i = 0; i < n_in; ++i) {
        switch (in_sizes[i]) {
            case 69632:   x        = (const float*)d_in[i]; break;
            case 32768:   ip       = (const int*)  d_in[i]; break;
            case 8192:    port     = (const int*)  d_in[i]; break;
            case 256:     ip_emb   = (const float*)d_in[i]; break;
            case 280000:  port_emb = (const float*)d_in[i]; break;
            case 135168:  Wih0     = (const float*)d_in[i]; break;
            case 4194304: if (nbig  < 3) big[nbig++]   = (const float*)d_in[i]; break;
            case 4096:    if (nbias < 4) bias[nbias++] = (const float*)d_in[i]; break;
            case 2048:    if (nst2  < 2) st2[nst2++]   = (const float*)d_in[i]; break;
            default: break;
        }
    }
    if (nbig == 3 && nbias == 4 && nst2 == 2 && x && ip && port &&
        ip_emb && port_emb && Wih0) {
        Whh0 = big[0]; Wih1 = big[1]; Whh1 = big[2];
        bih0 = bias[0]; bhh0 = bias[1]; bih1 = bias[2]; bhh1 = bias[3];
        hidden = st2[0]; cell = st2[1];
    } else {
        x        = (const float*)d_in[0];
        ip       = (const int*)  d_in[1];
        port     = (const int*)  d_in[2];
        hidden   = (const float*)d_in[3];
        cell     = (const float*)d_in[4];
        ip_emb   = (const float*)d_in[5];
        port_emb = (const float*)d_in[6];
        Wih0     = (const float*)d_in[7];
        Whh0     = (const float*)d_in[8];
        bih0     = (const float*)d_in[9];
        bhh0     = (const float*)d_in[10];
        Wih1     = (const float*)d_in[11];
        Whh1     = (const float*)d_in[12];
        bih1     = (const float*)d_in[13];
        bhh1     = (const float*)d_in[14];
    }
    float* out = (float*)d_out;
    int write_state = (out_size >= (int)(T_STEPS * H + 4 * H)) ? 1 : 0;

    cudaFuncSetAttribute(lstm_kernel,
                         cudaFuncAttributeMaxDynamicSharedMemorySize,
                         SMEM_BYTES);

    init_kernel<<<1, 1024>>>(hidden);
    g0_kernel<<<T_STEPS / 8, 256>>>(x, ip, port, ip_emb, port_emb,
                                    Wih0, bih0, bhh0);
    lstm_kernel<<<GRID, THREADS, SMEM_BYTES>>>(Whh0, Wih1, Whh1,
                                               bih1, bhh1, cell, out,
                                               write_state);
}